// round 1
// baseline (speedup 1.0000x reference)
#include <cuda_runtime.h>
#include <cstdint>

// Internal heap nodes: g_tree[i] = sum of subtree at heap index i, i in [1, 2^24).
// Leaves (level 24) live in the input array itself and are addressed as
// heap index - 2^24. 64 MB static device array (allowed; no cudaMalloc).
#define BOUND (1 << 24)
__device__ float g_tree[BOUND];

// ---------------------------------------------------------------------------
// Kernel A: each block reduces a 4096-leaf chunk, producing heap levels 23..12.
// After k pairwise reductions (k=1..12) the block holds 4096>>k nodes of
// global level (24-k), written at heap base (1<<(24-k)) + blockIdx.x*(4096>>k).
// Pairing is identical to the reference's reshape(-1,2).sum(axis=1), so all
// partial sums are bitwise-exact matches.
// ---------------------------------------------------------------------------
__global__ __launch_bounds__(256) void build_lower(const float* __restrict__ leaf) {
    __shared__ float s[8192];
    const int b = blockIdx.x;
    const int t = threadIdx.x;

    // Load 4096 leaves via float4 (coalesced).
    const float4* l4 = reinterpret_cast<const float4*>(leaf + (size_t)b * 4096);
    float4* s4 = reinterpret_cast<float4*>(s);
#pragma unroll
    for (int i = t; i < 1024; i += 256) s4[i] = l4[i];
    __syncthreads();

    int src = 0;
#pragma unroll
    for (int k = 1; k <= 12; ++k) {
        const int n = 4096 >> k;
        const int dst = (k & 1) ? 4096 : 0;
        const unsigned heapBase = (1u << (24 - k)) + (unsigned)b * n;
        for (int i = t; i < n; i += 256) {
            float v = s[src + 2 * i] + s[src + 2 * i + 1];
            s[dst + i] = v;
            g_tree[heapBase + i] = v;
        }
        __syncthreads();
        src = dst;
    }
}

// ---------------------------------------------------------------------------
// Kernel B: single block finishes the top. Reads level 12 (4096 nodes at heap
// [4096, 8192)) and produces levels 11..0 (heap [1, 4096)). Root at g_tree[1].
// ---------------------------------------------------------------------------
__global__ __launch_bounds__(1024) void build_top() {
    __shared__ float s[8192];
    const int t = threadIdx.x;
    float4* s4 = reinterpret_cast<float4*>(s);
    const float4* g4 = reinterpret_cast<const float4*>(&g_tree[4096]);
    for (int i = t; i < 1024; i += 1024) s4[i] = g4[i];
    __syncthreads();

    int src = 0;
#pragma unroll
    for (int k = 1; k <= 12; ++k) {
        const int n = 4096 >> k;
        const int dst = (k & 1) ? 4096 : 0;
        const unsigned heapBase = 1u << (12 - k);
        for (int i = t; i < n; i += 1024) {
            float v = s[src + 2 * i] + s[src + 2 * i + 1];
            s[dst + i] = v;
            g_tree[heapBase + i] = v;
        }
        __syncthreads();
        src = dst;
    }
}

// ---------------------------------------------------------------------------
// Descent: one thread per query. Top 13 heap levels (8192 floats = 32 KB) are
// staged into shared memory per block: 12 descent steps hit smem (29 cyc),
// 11 steps hit g_tree (L2-resident), final step reads the leaf array.
// Arithmetic is the exact sequence of the reference:
//   value = frac * tree[1];  each step: direct = (lsons < value);
//   value -= direct ? lsons : 0;  index = index*2 + direct;
// ---------------------------------------------------------------------------
__global__ __launch_bounds__(256) void descend(const float* __restrict__ leaf,
                                               const float* __restrict__ frac,
                                               float* __restrict__ out,
                                               int batch) {
    __shared__ float s[8192];
    const int t = threadIdx.x;
    float4* s4 = reinterpret_cast<float4*>(s);
    const float4* g4 = reinterpret_cast<const float4*>(g_tree);
#pragma unroll
    for (int i = t; i < 2048; i += 256) s4[i] = g4[i];
    __syncthreads();

    const int q = blockIdx.x * 256 + t;
    if (q >= batch) return;

    float v = frac[q] * s[1];
    int idx = 1;

    // Steps 0..11: indices in [2, 8192) -> shared memory.
#pragma unroll
    for (int d = 0; d < 12; ++d) {
        idx <<= 1;
        float l = s[idx];
        bool r = (l < v);
        v = r ? (v - l) : v;
        idx += (int)r;
    }
    // Steps 12..22: indices in [2^13, 2^24) -> global internal nodes.
#pragma unroll
    for (int d = 0; d < 11; ++d) {
        idx <<= 1;
        float l = __ldg(&g_tree[idx]);
        bool r = (l < v);
        v = r ? (v - l) : v;
        idx += (int)r;
    }
    // Step 23: indices in [2^24, 2^25) -> leaves.
    idx <<= 1;
    {
        float l = __ldg(&leaf[idx - BOUND]);
        bool r = (l < v);
        idx += (int)r;
    }

    const int leafIdx = idx - BOUND;
    out[q] = (float)leafIdx;             // index output (exact in f32, < 2^24)
    out[batch + q] = leaf[leafIdx];      // priorities output
}

extern "C" void kernel_launch(void* const* d_in, const int* in_sizes, int n_in,
                              void* d_out, int out_size) {
    const float* leaf = (const float*)d_in[0];
    const float* frac = (const float*)d_in[1];
    float* out = (float*)d_out;
    const int batch = in_sizes[1];

    build_lower<<<BOUND / 4096, 256>>>(leaf);
    build_top<<<1, 1024>>>();
    descend<<<(batch + 255) / 256, 256>>>(leaf, frac, out, batch);
}

// round 2
// speedup vs baseline: 1.4177x; 1.4177x over previous
#include <cuda_runtime.h>
#include <cstdint>

// Internal heap nodes, heap-indexed: g_tree[i] = subtree sum at heap index i.
// Only levels 12..23 (indices [4096, 2^24)) are materialized; levels 0..11 are
// rebuilt in shared memory by each descend block. Leaves (level 24) stay in
// the input array, addressed as heap index - 2^24.
#define BOUND (1 << 24)
__device__ float g_tree[BOUND];

// ---------------------------------------------------------------------------
// Build: each block reduces 4096 contiguous leaves into heap levels 23..12
// using registers + warp shuffles (no smem ping-pong, no bank conflicts).
// Pairing/order is exactly reshape(-1,2).sum(axis=1): left + right with left
// at the lower index / lower lane -> bitwise-identical to the reference.
// ---------------------------------------------------------------------------
__global__ __launch_bounds__(256) void build_lower(const float* __restrict__ leaf) {
    const int b = blockIdx.x;
    const int t = threadIdx.x;
    const int lane = t & 31;
    const int w = t >> 5;
    __shared__ float s17[32];

    const float4* __restrict__ in = reinterpret_cast<const float4*>(leaf) + (size_t)b * 1024;

    // Per-level bases for this block (block owns 2^(L-12) nodes at level L).
    float* g23 = g_tree + (1u << 23) + (size_t)b * 2048;
    float* g22 = g_tree + (1u << 22) + (size_t)b * 1024;
    float* g21 = g_tree + (1u << 21) + (size_t)b * 512;
    float* g20 = g_tree + (1u << 20) + (size_t)b * 256;
    float* g19 = g_tree + (1u << 19) + (size_t)b * 128;
    float* g18 = g_tree + (1u << 18) + (size_t)b * 64;
    float* g17 = g_tree + (1u << 17) + (size_t)b * 32;

#pragma unroll
    for (int r = 0; r < 4; ++r) {
        const int q = r * 256 + t;          // quad index within block (l22 node id)
        float4 a = in[q];                   // dense, coalesced LDG.128
        float p0 = a.x + a.y;               // level-23 node 2q
        float p1 = a.z + a.w;               // level-23 node 2q+1
        reinterpret_cast<float2*>(g23)[q] = make_float2(p0, p1);  // coalesced 8B
        float v = p0 + p1;                  // level-22 node q
        g22[q] = v;                         // coalesced 4B

        // Warp covers l22 nodes [r*256 + w*32, +32): reduce 5 levels via shuffles.
        float u;
        u = __shfl_down_sync(0xffffffffu, v, 1);  v += u;   // even lanes: l21
        if (!(lane & 1))  g21[r * 128 + w * 16 + (lane >> 1)] = v;
        u = __shfl_down_sync(0xffffffffu, v, 2);  v += u;   // lane%4==0: l20
        if (!(lane & 3))  g20[r * 64 + w * 8 + (lane >> 2)] = v;
        u = __shfl_down_sync(0xffffffffu, v, 4);  v += u;   // lane%8==0: l19
        if (!(lane & 7))  g19[r * 32 + w * 4 + (lane >> 3)] = v;
        u = __shfl_down_sync(0xffffffffu, v, 8);  v += u;   // lane%16==0: l18
        if (!(lane & 15)) g18[r * 16 + w * 2 + (lane >> 4)] = v;
        u = __shfl_down_sync(0xffffffffu, v, 16); v += u;   // lane 0: l17
        if (lane == 0) { g17[r * 8 + w] = v; s17[r * 8 + w] = v; }
    }
    __syncthreads();

    // Warp 0 finishes levels 16..12 from the 32 level-17 values (in order).
    if (w == 0) {
        float v = s17[lane];
        float u;
        float* g16 = g_tree + (1u << 16) + (size_t)b * 16;
        float* g15 = g_tree + (1u << 15) + (size_t)b * 8;
        float* g14 = g_tree + (1u << 14) + (size_t)b * 4;
        float* g13 = g_tree + (1u << 13) + (size_t)b * 2;
        float* g12 = g_tree + (1u << 12) + (size_t)b;
        u = __shfl_down_sync(0xffffffffu, v, 1);  v += u;
        if (!(lane & 1))  g16[lane >> 1] = v;
        u = __shfl_down_sync(0xffffffffu, v, 2);  v += u;
        if (!(lane & 3))  g15[lane >> 2] = v;
        u = __shfl_down_sync(0xffffffffu, v, 4);  v += u;
        if (!(lane & 7))  g14[lane >> 3] = v;
        u = __shfl_down_sync(0xffffffffu, v, 8);  v += u;
        if (!(lane & 15)) g13[lane >> 4] = v;
        u = __shfl_down_sync(0xffffffffu, v, 16); v += u;
        if (lane == 0)    g12[0] = v;
    }
}

// ---------------------------------------------------------------------------
// Descend: each block stages heap levels 1..12 in smem (level 12 loaded from
// g_tree, levels 11..0 rebuilt locally — removes the serialized build_top
// kernel). Then per-thread root-to-leaf binary descent, arithmetic identical
// to the reference: direct = (lsons < value); value -= direct*lsons;
// index = 2*index + direct.
// ---------------------------------------------------------------------------
__global__ __launch_bounds__(512) void descend(const float* __restrict__ leaf,
                                               const float* __restrict__ frac,
                                               float* __restrict__ out,
                                               int batch) {
    __shared__ float s[8192];
    const int t = threadIdx.x;
    const int q = blockIdx.x * 512 + t;
    const float f = (q < batch) ? frac[q] : 0.0f;   // overlap with staging

    // Stage level 12 (heap [4096, 8192)) via float4.
    {
        float4* s4 = reinterpret_cast<float4*>(s);
        const float4* g4 = reinterpret_cast<const float4*>(g_tree);
#pragma unroll
        for (int i = t; i < 1024; i += 512) s4[1024 + i] = g4[1024 + i];
    }
    __syncthreads();

    // Rebuild levels 11..0 (heap indices [n, 2n) for n = 2048..1).
#pragma unroll
    for (int n = 2048; n >= 1; n >>= 1) {
        for (int i = t; i < n; i += 512) {
            s[n + i] = s[2 * (n + i)] + s[2 * (n + i) + 1];
        }
        __syncthreads();
    }

    if (q >= batch) return;

    float v = f * s[1];
    int idx = 1;

    // Steps 0..11: smem (heap indices [2, 8192)).
#pragma unroll
    for (int d = 0; d < 12; ++d) {
        idx <<= 1;
        float l = s[idx];
        bool r = (l < v);
        v = r ? (v - l) : v;
        idx += (int)r;
    }
    // Steps 12..22: global internal nodes (heap [8192, 2^24)).
#pragma unroll
    for (int d = 0; d < 11; ++d) {
        idx <<= 1;
        float l = __ldg(&g_tree[idx]);
        bool r = (l < v);
        v = r ? (v - l) : v;
        idx += (int)r;
    }
    // Step 23: leaves.
    idx <<= 1;
    {
        float l = __ldg(&leaf[idx - BOUND]);
        bool r = (l < v);
        idx += (int)r;
    }

    const int leafIdx = idx - BOUND;
    out[q] = (float)leafIdx;             // exact in f32 (< 2^24)
    out[batch + q] = leaf[leafIdx];
}

extern "C" void kernel_launch(void* const* d_in, const int* in_sizes, int n_in,
                              void* d_out, int out_size) {
    const float* leaf = (const float*)d_in[0];
    const float* frac = (const float*)d_in[1];
    float* out = (float*)d_out;
    const int batch = in_sizes[1];

    build_lower<<<BOUND / 4096, 256>>>(leaf);
    descend<<<(batch + 511) / 512, 512>>>(leaf, frac, out, batch);
}

// round 3
// speedup vs baseline: 1.9246x; 1.3576x over previous
#include <cuda_runtime.h>
#include <cstdint>

// Internal heap nodes, heap-indexed. Only levels 12..20 (heap [4096, 2^21))
// are materialized; levels 21..23 are recomputed from leaves in the descent's
// final 64B burst, and levels 0..11 are rebuilt in smem per descend block.
// All sums use the identical left+right pairing as the reference's
// reshape(-1,2).sum(axis=1), so every comparison is bitwise-exact.
#define BOUND (1 << 24)
__device__ float g_tree[1 << 21];   // only [4096, 2^21) used; 8 MB

// ---------------------------------------------------------------------------
// Build: each block reduces 4096 contiguous leaves; stores only levels 20..12.
// ---------------------------------------------------------------------------
__global__ __launch_bounds__(256) void build_lower(const float* __restrict__ leaf) {
    const int b = blockIdx.x;           // 4096 blocks
    const int t = threadIdx.x;
    const int lane = t & 31;
    const int w = t >> 5;               // 8 warps
    __shared__ float s17[32];

    const float4* __restrict__ in = reinterpret_cast<const float4*>(leaf) + (size_t)b * 1024;

    float* g20 = g_tree + (1u << 20) + (size_t)b * 256;
    float* g19 = g_tree + (1u << 19) + (size_t)b * 128;
    float* g18 = g_tree + (1u << 18) + (size_t)b * 64;
    float* g17 = g_tree + (1u << 17) + (size_t)b * 32;

#pragma unroll
    for (int r = 0; r < 4; ++r) {
        const int q = r * 256 + t;                    // level-22 node id in block
        float4 a = in[q];                             // coalesced LDG.128
        float v = (a.x + a.y) + (a.z + a.w);          // level-22 value (exact pairing)
        float u;
        u = __shfl_down_sync(0xffffffffu, v, 1);  v += u;   // level 21 (not stored)
        u = __shfl_down_sync(0xffffffffu, v, 2);  v += u;   // level 20
        if (!(lane & 3))  g20[r * 64 + w * 8 + (lane >> 2)] = v;
        u = __shfl_down_sync(0xffffffffu, v, 4);  v += u;   // level 19
        if (!(lane & 7))  g19[r * 32 + w * 4 + (lane >> 3)] = v;
        u = __shfl_down_sync(0xffffffffu, v, 8);  v += u;   // level 18
        if (!(lane & 15)) g18[r * 16 + w * 2 + (lane >> 4)] = v;
        u = __shfl_down_sync(0xffffffffu, v, 16); v += u;   // level 17
        if (lane == 0) { g17[r * 8 + w] = v; s17[r * 8 + w] = v; }
    }
    __syncthreads();

    // Warp 0 finishes levels 16..12 from the 32 level-17 values.
    if (w == 0) {
        float v = s17[lane];
        float u;
        float* g16 = g_tree + (1u << 16) + (size_t)b * 16;
        float* g15 = g_tree + (1u << 15) + (size_t)b * 8;
        float* g14 = g_tree + (1u << 14) + (size_t)b * 4;
        float* g13 = g_tree + (1u << 13) + (size_t)b * 2;
        float* g12 = g_tree + (1u << 12) + (size_t)b;
        u = __shfl_down_sync(0xffffffffu, v, 1);  v += u;
        if (!(lane & 1))  g16[lane >> 1] = v;
        u = __shfl_down_sync(0xffffffffu, v, 2);  v += u;
        if (!(lane & 3))  g15[lane >> 2] = v;
        u = __shfl_down_sync(0xffffffffu, v, 4);  v += u;
        if (!(lane & 7))  g14[lane >> 3] = v;
        u = __shfl_down_sync(0xffffffffu, v, 8);  v += u;
        if (!(lane & 15)) g13[lane >> 4] = v;
        u = __shfl_down_sync(0xffffffffu, v, 16); v += u;
        if (lane == 0)    g12[0] = v;
    }
}

// ---------------------------------------------------------------------------
// Descend: smem levels 1..12, then levels 13..20 two-per-round (3 speculative
// independent loads per round = half the dependent latency chain), then one
// 64B burst of the 16 leaves under the level-20 node resolves levels 21..24
// AND the priority gather entirely in registers.
// ---------------------------------------------------------------------------
__global__ __launch_bounds__(256) void descend(const float* __restrict__ leaf,
                                               const float* __restrict__ frac,
                                               float* __restrict__ out,
                                               int batch) {
    __shared__ float s[8192];
    const int t = threadIdx.x;
    const int q = blockIdx.x * 256 + t;
    const float f = (q < batch) ? frac[q] : 0.0f;

    // Stage level 12 (heap [4096, 8192)).
    {
        float4* s4p = reinterpret_cast<float4*>(s);
        const float4* g4 = reinterpret_cast<const float4*>(g_tree);
#pragma unroll
        for (int i = t; i < 1024; i += 256) s4p[1024 + i] = g4[1024 + i];
    }
    __syncthreads();
    // Rebuild levels 11..0.
#pragma unroll
    for (int n = 2048; n >= 1; n >>= 1) {
        for (int i = t; i < n; i += 256)
            s[n + i] = s[2 * (n + i)] + s[2 * (n + i) + 1];
        __syncthreads();
    }

    if (q >= batch) return;

    float v = f * s[1];
    int idx = 1;

    // Levels 1..12: smem.
#pragma unroll
    for (int d = 0; d < 12; ++d) {
        idx <<= 1;
        float l = s[idx];
        bool r = (l < v);
        v = r ? (v - l) : v;
        idx += (int)r;
    }

    // Levels 13..20: 4 rounds of 2 levels. tree[2i] is the left child;
    // tree[4i], tree[4i+2] are the left children of both possible children.
#pragma unroll
    for (int d = 0; d < 4; ++d) {
        float a  = __ldg(&g_tree[2 * idx]);
        float bl = __ldg(&g_tree[4 * idx]);
        float cl = __ldg(&g_tree[4 * idx + 2]);
        bool r1 = (a < v);  v = r1 ? (v - a) : v;
        float l2 = r1 ? cl : bl;
        bool r2 = (l2 < v); v = r2 ? (v - l2) : v;
        idx = 4 * idx + 2 * (int)r1 + (int)r2;
    }

    // idx at level 20. Burst the 16 leaves under it (64B aligned).
    const int base = (idx << 4) - BOUND;
    const float4* lp = reinterpret_cast<const float4*>(leaf + base);
    float4 A = __ldg(lp);
    float4 B = __ldg(lp + 1);
    float4 C = __ldg(lp + 2);
    float4 D = __ldg(lp + 3);

    // Recompute levels 23/22/21 with the exact reference pairing.
    float s8_0 = A.x + A.y, s8_1 = A.z + A.w, s8_2 = B.x + B.y, s8_3 = B.z + B.w;
    float s8_4 = C.x + C.y, s8_5 = C.z + C.w, s8_6 = D.x + D.y, s8_7 = D.z + D.w;
    float s4_0 = s8_0 + s8_1, s4_1 = s8_2 + s8_3, s4_2 = s8_4 + s8_5, s4_3 = s8_6 + s8_7;
    float s2_0 = s4_0 + s4_1;

    // Level 21 decision.
    bool r1 = (s2_0 < v); v = r1 ? (v - s2_0) : v;
    // Level 22.
    float l22 = r1 ? s4_2 : s4_0;
    bool r2 = (l22 < v); v = r2 ? (v - l22) : v;
    // Level 23.
    float l23 = r1 ? (r2 ? s8_6 : s8_4) : (r2 ? s8_2 : s8_0);
    bool r3 = (l23 < v); v = r3 ? (v - l23) : v;
    // Level 24 (leaf) — narrow down the chosen pair via selects.
    float4 P = r1 ? C : A;
    float4 Q = r1 ? D : B;
    float4 R = r2 ? Q : P;
    float e0 = r3 ? R.z : R.x;
    float e1 = r3 ? R.w : R.y;
    bool r4 = (e0 < v);
    float prio = r4 ? e1 : e0;

    const int leafIdx = base + 8 * (int)r1 + 4 * (int)r2 + 2 * (int)r3 + (int)r4;
    out[q] = (float)leafIdx;         // exact in f32 (< 2^24)
    out[batch + q] = prio;           // priority, no extra gather
}

extern "C" void kernel_launch(void* const* d_in, const int* in_sizes, int n_in,
                              void* d_out, int out_size) {
    const float* leaf = (const float*)d_in[0];
    const float* frac = (const float*)d_in[1];
    float* out = (float*)d_out;
    const int batch = in_sizes[1];

    build_lower<<<BOUND / 4096, 256>>>(leaf);
    descend<<<(batch + 255) / 256, 256>>>(leaf, frac, out, batch);
}

// round 4
// speedup vs baseline: 2.1346x; 1.1091x over previous
#include <cuda_runtime.h>
#include <cstdint>

// Internal heap nodes, heap-indexed. Only levels 12..20 (heap [4096, 2^21))
// are materialized; levels 21..23 are recomputed in registers from a 64B leaf
// burst; levels 0..11 are rebuilt in smem per descend block. All sums use the
// identical left+right pairing as the reference's reshape(-1,2).sum(axis=1),
// so every comparison is bitwise-exact.
#define BOUND (1 << 24)
__device__ float g_tree[1 << 21];   // only [4096, 2^21) used; 8 MB

// ---------------------------------------------------------------------------
// Build: each block reduces 4096 contiguous leaves; stores only levels 20..12.
// ---------------------------------------------------------------------------
__global__ __launch_bounds__(256) void build_lower(const float* __restrict__ leaf) {
    const int b = blockIdx.x;           // 4096 blocks
    const int t = threadIdx.x;
    const int lane = t & 31;
    const int w = t >> 5;               // 8 warps
    __shared__ float s17[32];

    const float4* __restrict__ in = reinterpret_cast<const float4*>(leaf) + (size_t)b * 1024;

    float* g20 = g_tree + (1u << 20) + (size_t)b * 256;
    float* g19 = g_tree + (1u << 19) + (size_t)b * 128;
    float* g18 = g_tree + (1u << 18) + (size_t)b * 64;
    float* g17 = g_tree + (1u << 17) + (size_t)b * 32;

#pragma unroll
    for (int r = 0; r < 4; ++r) {
        const int q = r * 256 + t;                    // level-22 node id in block
        float4 a = in[q];                             // coalesced LDG.128
        float v = (a.x + a.y) + (a.z + a.w);          // level-22 value (exact pairing)
        float u;
        u = __shfl_down_sync(0xffffffffu, v, 1);  v += u;   // level 21 (not stored)
        u = __shfl_down_sync(0xffffffffu, v, 2);  v += u;   // level 20
        if (!(lane & 3))  g20[r * 64 + w * 8 + (lane >> 2)] = v;
        u = __shfl_down_sync(0xffffffffu, v, 4);  v += u;   // level 19
        if (!(lane & 7))  g19[r * 32 + w * 4 + (lane >> 3)] = v;
        u = __shfl_down_sync(0xffffffffu, v, 8);  v += u;   // level 18
        if (!(lane & 15)) g18[r * 16 + w * 2 + (lane >> 4)] = v;
        u = __shfl_down_sync(0xffffffffu, v, 16); v += u;   // level 17
        if (lane == 0) { g17[r * 8 + w] = v; s17[r * 8 + w] = v; }
    }
    __syncthreads();

    if (w == 0) {
        float v = s17[lane];
        float u;
        float* g16 = g_tree + (1u << 16) + (size_t)b * 16;
        float* g15 = g_tree + (1u << 15) + (size_t)b * 8;
        float* g14 = g_tree + (1u << 14) + (size_t)b * 4;
        float* g13 = g_tree + (1u << 13) + (size_t)b * 2;
        float* g12 = g_tree + (1u << 12) + (size_t)b;
        u = __shfl_down_sync(0xffffffffu, v, 1);  v += u;
        if (!(lane & 1))  g16[lane >> 1] = v;
        u = __shfl_down_sync(0xffffffffu, v, 2);  v += u;
        if (!(lane & 3))  g15[lane >> 2] = v;
        u = __shfl_down_sync(0xffffffffu, v, 4);  v += u;
        if (!(lane & 7))  g14[lane >> 3] = v;
        u = __shfl_down_sync(0xffffffffu, v, 8);  v += u;
        if (!(lane & 15)) g13[lane >> 4] = v;
        u = __shfl_down_sync(0xffffffffu, v, 16); v += u;
        if (lane == 0)    g12[0] = v;
    }
}

// ---------------------------------------------------------------------------
// Descend: 2 queries per thread (interleaved => 2x MLP at fixed warp count).
// Levels 1..12 in smem; levels 13..20 in rounds of (3,3,2) levels via
// speculative left-child loads (7/7/3 independent loads per round per query);
// levels 21..24 + priority resolved in registers from one 64B leaf burst.
// ---------------------------------------------------------------------------
#define QPT 2
__global__ __launch_bounds__(256) void descend(const float* __restrict__ leaf,
                                               const float* __restrict__ frac,
                                               float* __restrict__ out,
                                               int batch) {
    __shared__ float s[8192];
    const int t = threadIdx.x;
    const int qbase = blockIdx.x * 256 * QPT + t;

    float f[QPT];
#pragma unroll
    for (int j = 0; j < QPT; ++j) {
        int q = qbase + j * 256;
        f[j] = (q < batch) ? frac[q] : 0.0f;    // overlap with staging
    }

    // Stage level 12 (heap [4096, 8192)).
    {
        float4* s4p = reinterpret_cast<float4*>(s);
        const float4* g4 = reinterpret_cast<const float4*>(g_tree);
#pragma unroll
        for (int i = t; i < 1024; i += 256) s4p[1024 + i] = g4[1024 + i];
    }
    __syncthreads();
    // Rebuild levels 11..0.
#pragma unroll
    for (int n = 2048; n >= 1; n >>= 1) {
        for (int i = t; i < n; i += 256)
            s[n + i] = s[2 * (n + i)] + s[2 * (n + i) + 1];
        __syncthreads();
    }

    float v[QPT];
    int idx[QPT];
#pragma unroll
    for (int j = 0; j < QPT; ++j) { v[j] = f[j] * s[1]; idx[j] = 1; }

    // Levels 1..12: smem (both queries interleaved; LDS pipelined).
#pragma unroll
    for (int d = 0; d < 12; ++d) {
        float l[QPT];
#pragma unroll
        for (int j = 0; j < QPT; ++j) { idx[j] <<= 1; l[j] = s[idx[j]]; }
#pragma unroll
        for (int j = 0; j < QPT; ++j) {
            bool r = (l[j] < v[j]);
            v[j] = r ? (v[j] - l[j]) : v[j];
            idx[j] += (int)r;
        }
    }

    // Levels 13..20: rounds of 3, 3, 2 levels.
#pragma unroll
    for (int round = 0; round < 2; ++round) {   // two 3-level rounds
        float a[QPT], b0[QPT], b2[QPT], c0[QPT], c2[QPT], c4[QPT], c6[QPT];
#pragma unroll
        for (int j = 0; j < QPT; ++j) {
            int i = idx[j];
            a[j]  = __ldg(&g_tree[2 * i]);
            b0[j] = __ldg(&g_tree[4 * i]);
            b2[j] = __ldg(&g_tree[4 * i + 2]);
            c0[j] = __ldg(&g_tree[8 * i]);
            c2[j] = __ldg(&g_tree[8 * i + 2]);
            c4[j] = __ldg(&g_tree[8 * i + 4]);
            c6[j] = __ldg(&g_tree[8 * i + 6]);
        }
#pragma unroll
        for (int j = 0; j < QPT; ++j) {
            bool r1 = (a[j] < v[j]);  v[j] = r1 ? (v[j] - a[j]) : v[j];
            float l2 = r1 ? b2[j] : b0[j];
            bool r2 = (l2 < v[j]);    v[j] = r2 ? (v[j] - l2) : v[j];
            float l3 = r1 ? (r2 ? c6[j] : c4[j]) : (r2 ? c2[j] : c0[j]);
            bool r3 = (l3 < v[j]);    v[j] = r3 ? (v[j] - l3) : v[j];
            idx[j] = 8 * idx[j] + 4 * (int)r1 + 2 * (int)r2 + (int)r3;
        }
    }
    {   // one 2-level round -> level 20
        float a[QPT], b0[QPT], b2[QPT];
#pragma unroll
        for (int j = 0; j < QPT; ++j) {
            int i = idx[j];
            a[j]  = __ldg(&g_tree[2 * i]);
            b0[j] = __ldg(&g_tree[4 * i]);
            b2[j] = __ldg(&g_tree[4 * i + 2]);
        }
#pragma unroll
        for (int j = 0; j < QPT; ++j) {
            bool r1 = (a[j] < v[j]);  v[j] = r1 ? (v[j] - a[j]) : v[j];
            float l2 = r1 ? b2[j] : b0[j];
            bool r2 = (l2 < v[j]);    v[j] = r2 ? (v[j] - l2) : v[j];
            idx[j] = 4 * idx[j] + 2 * (int)r1 + (int)r2;
        }
    }

    // Leaf bursts for both queries (8 independent LDG.128 in flight).
    float4 A[QPT], B[QPT], C[QPT], D[QPT];
    int base[QPT];
#pragma unroll
    for (int j = 0; j < QPT; ++j) {
        base[j] = (idx[j] << 4) - BOUND;
        const float4* lp = reinterpret_cast<const float4*>(leaf + base[j]);
        A[j] = __ldg(lp);
        B[j] = __ldg(lp + 1);
        C[j] = __ldg(lp + 2);
        D[j] = __ldg(lp + 3);
    }

#pragma unroll
    for (int j = 0; j < QPT; ++j) {
        float s8_0 = A[j].x + A[j].y, s8_2 = B[j].x + B[j].y;
        float s8_4 = C[j].x + C[j].y, s8_6 = D[j].x + D[j].y;
        float s4_0 = s8_0 + (A[j].z + A[j].w), s4_1 = s8_2 + (B[j].z + B[j].w);
        float s4_2 = s8_4 + (C[j].z + C[j].w);
        float s2_0 = s4_0 + s4_1;
        float vv = v[j];

        bool r1 = (s2_0 < vv); vv = r1 ? (vv - s2_0) : vv;      // level 21
        float l22 = r1 ? s4_2 : s4_0;
        bool r2 = (l22 < vv);  vv = r2 ? (vv - l22) : vv;       // level 22
        float l23 = r1 ? (r2 ? s8_6 : s8_4) : (r2 ? s8_2 : s8_0);
        bool r3 = (l23 < vv);  vv = r3 ? (vv - l23) : vv;       // level 23
        float4 P = r1 ? C[j] : A[j];
        float4 Q = r1 ? D[j] : B[j];
        float4 R = r2 ? Q : P;
        float e0 = r3 ? R.z : R.x;
        float e1 = r3 ? R.w : R.y;
        bool r4 = (e0 < vv);                                    // level 24
        float prio = r4 ? e1 : e0;

        int leafIdx = base[j] + 8 * (int)r1 + 4 * (int)r2 + 2 * (int)r3 + (int)r4;
        int q = qbase + j * 256;
        if (q < batch) {
            out[q] = (float)leafIdx;      // exact in f32 (< 2^24)
            out[batch + q] = prio;
        }
    }
}

extern "C" void kernel_launch(void* const* d_in, const int* in_sizes, int n_in,
                              void* d_out, int out_size) {
    const float* leaf = (const float*)d_in[0];
    const float* frac = (const float*)d_in[1];
    float* out = (float*)d_out;
    const int batch = in_sizes[1];

    build_lower<<<BOUND / 4096, 256>>>(leaf);
    descend<<<(batch + 256 * QPT - 1) / (256 * QPT), 256>>>(leaf, frac, out, batch);
}